// round 14
// baseline (speedup 1.0000x reference)
#include <cuda_runtime.h>
#include <cuda_bf16.h>
#include <cuda_fp16.h>
#include <cstdint>

// Problem constants (fixed by the dataset)
#define DHEAD 128
#define MPROJ 128
#define NQ    4096
#define NK    8192
#define SCALE_CONST 0.009791516698f  // sqrt(pi/2)/128

// ---------------- device-global scratch (pre-swizzled SW128 slab layout) -------
// g_q / g_signs: fp16, 128-row tiles of 32KB; two 16KB slabs (64 cols each);
//                slab offset = sw128(row*128 + col*2).
__device__ __half g_signs[NK * MPROJ];
__device__ float  g_nscale[NK];
__device__ __half g_q[NQ * MPROJ];

__device__ __forceinline__ uint32_t sw128(uint32_t x) { return x ^ ((x >> 3) & 0x70); }

// ---- packed fp32x2 helpers (sm_100+ PTX; doubles fp32 FMA throughput) ----
__device__ __forceinline__ unsigned long long pack2(float x) {
    unsigned long long r;
    uint32_t b = __float_as_uint(x);
    asm("mov.b64 %0, {%1, %1};" : "=l"(r) : "r"(b));
    return r;
}
__device__ __forceinline__ unsigned long long fma2(unsigned long long a,
                                                   unsigned long long b,
                                                   unsigned long long c) {
    unsigned long long d;
    asm("fma.rn.f32x2 %0, %1, %2, %3;" : "=l"(d) : "l"(a), "l"(b), "l"(c));
    return d;
}

// ================================================================================
// Prep: fp32 GEMM rows @ S^T with packed f32x2 over COLUMN PAIRS (per-element
// accumulation order identical to prior passing rounds: serial k ascending —
// bit-identical sign decisions). Block = 32 rows x 64 cols, 128 threads,
// 2 rows x 8 cols (4 col-pairs) per thread. S stored TRANSPOSED in smem so
// column pairs are contiguous.
//   grid.x [0,256): residual -> signs (fp16 ±1, swizzled) + nscale
//   grid.x [256,384): query  -> q_proj (fp16, swizzled)
//   grid.y: column half (0: cols 0-63, 1: cols 64-127)
// ================================================================================
#define PREP_ROWS 32
#define PREP_COLS 64
#define PREP_THREADS 128
#define PADA 132     // Ash row pitch (floats), 16B aligned
#define PADT 68      // SshT row pitch (floats), 16B aligned (68*4=272=17*16)
#define PREP_SMEM_BYTES ((PREP_ROWS * PADA + DHEAD * PADT) * 4)

__global__ __launch_bounds__(PREP_THREADS)
void qjl_prep_kernel(const float* __restrict__ query,
                     const float* __restrict__ residual,
                     const float* __restrict__ S)
{
    extern __shared__ float smf[];
    float* Ash  = smf;                        // [32][132]  row-major (row, k)
    float* SshT = smf + PREP_ROWS * PADA;     // [128][68]  (k, local col j)

    const int tid = threadIdx.x;
    const bool is_res = (blockIdx.x < (NK / PREP_ROWS));
    const int rbase = is_res ? blockIdx.x * PREP_ROWS
                             : (blockIdx.x - NK / PREP_ROWS) * PREP_ROWS;
    const int colbase = blockIdx.y * PREP_COLS;
    const float* src = is_res ? residual : query;

    // ---- fill A rows (row-major) ----
    const float4* gA = (const float4*)(src + (size_t)rbase * DHEAD);
    #pragma unroll
    for (int idx = tid; idx < PREP_ROWS * 32; idx += PREP_THREADS) {
        int r = idx >> 5, c4 = idx & 31;
        *(float4*)(Ash + r * PADA + c4 * 4) = gA[idx];
    }
    // ---- fill S transposed: SshT[k][j] = S[colbase + j][k] ----
    const float4* gS = (const float4*)(S + (size_t)colbase * DHEAD);
    #pragma unroll
    for (int idx = tid; idx < PREP_COLS * 32; idx += PREP_THREADS) {
        int j = idx >> 5, k4 = idx & 31;
        float4 v = gS[idx];
        SshT[(4 * k4 + 0) * PADT + j] = v.x;
        SshT[(4 * k4 + 1) * PADT + j] = v.y;
        SshT[(4 * k4 + 2) * PADT + j] = v.z;
        SshT[(4 * k4 + 3) * PADT + j] = v.w;
    }
    __syncthreads();

    // norms: once per row (col-half 0 only); same serial order as prior rounds
    if (is_res && blockIdx.y == 0 && tid < PREP_ROWS) {
        float s = 0.f;
        #pragma unroll
        for (int k4 = 0; k4 < 32; k4++) {
            float4 a = *(const float4*)(Ash + tid * PADA + k4 * 4);
            s += a.x * a.x + a.y * a.y + a.z * a.z + a.w * a.w;
        }
        g_nscale[rbase + tid] = sqrtf(s) * SCALE_CONST;
    }

    const int rg = tid & 15;   // 2 rows per thread
    const int cg = tid >> 4;   // 8 cols (4 pairs) per thread

    unsigned long long acc2[2][4];
    #pragma unroll
    for (int i = 0; i < 2; i++)
        #pragma unroll
        for (int p = 0; p < 4; p++) acc2[i][p] = 0ull;

    const float* arow0 = Ash + (2 * rg) * PADA;
    const float* arow1 = arow0 + PADA;
    const float* bcol  = SshT + 8 * cg;

    #pragma unroll 4
    for (int k4 = 0; k4 < 32; k4++) {
        float4 a0 = *(const float4*)(arow0 + k4 * 4);
        float4 a1 = *(const float4*)(arow1 + k4 * 4);
        #pragma unroll
        for (int d = 0; d < 4; d++) {
            float a0d = (d == 0) ? a0.x : (d == 1) ? a0.y : (d == 2) ? a0.z : a0.w;
            float a1d = (d == 0) ? a1.x : (d == 1) ? a1.y : (d == 2) ? a1.z : a1.w;
            unsigned long long aa0 = pack2(a0d);
            unsigned long long aa1 = pack2(a1d);
            const ulonglong2* bp =
                (const ulonglong2*)(bcol + (size_t)(4 * k4 + d) * PADT);
            ulonglong2 b01 = bp[0];   // cols (0,1),(2,3) of this thread's 8
            ulonglong2 b23 = bp[1];   // cols (4,5),(6,7)
            acc2[0][0] = fma2(aa0, b01.x, acc2[0][0]);
            acc2[0][1] = fma2(aa0, b01.y, acc2[0][1]);
            acc2[0][2] = fma2(aa0, b23.x, acc2[0][2]);
            acc2[0][3] = fma2(aa0, b23.y, acc2[0][3]);
            acc2[1][0] = fma2(aa1, b01.x, acc2[1][0]);
            acc2[1][1] = fma2(aa1, b01.y, acc2[1][1]);
            acc2[1][2] = fma2(aa1, b23.x, acc2[1][2]);
            acc2[1][3] = fma2(aa1, b23.y, acc2[1][3]);
        }
    }

    // unpack: low half = even col, high half = odd col
    float acc[2][8];
    #pragma unroll
    for (int i = 0; i < 2; i++)
        #pragma unroll
        for (int p = 0; p < 4; p++) {
            acc[i][2 * p]     = __uint_as_float((uint32_t)(acc2[i][p] & 0xffffffffull));
            acc[i][2 * p + 1] = __uint_as_float((uint32_t)(acc2[i][p] >> 32));
        }

    const int col8 = colbase + 8 * cg;     // global col base (0..120)
    if (is_res) {
        #pragma unroll
        for (int i = 0; i < 2; i++) {
            union { __half h[8]; uint4 u; } pk;
            #pragma unroll
            for (int j = 0; j < 8; j++)
                pk.h[j] = __float2half(acc[i][j] >= 0.f ? 1.f : -1.f);
            int row = rbase + 2 * rg + i;
            uint32_t off = (uint32_t)(row >> 7) * 32768u
                         + (uint32_t)(col8 >> 6) * 16384u
                         + sw128((uint32_t)(row & 127) * 128u + (uint32_t)(col8 & 63) * 2u);
            *(uint4*)((char*)g_signs + off) = pk.u;
        }
    } else {
        #pragma unroll
        for (int i = 0; i < 2; i++) {
            union { __half h[8]; uint4 u; } ph;
            #pragma unroll
            for (int j = 0; j < 8; j++)
                ph.h[j] = __float2half(acc[i][j]);
            int row = rbase + 2 * rg + i;
            uint32_t off = (uint32_t)(row >> 7) * 32768u
                         + (uint32_t)(col8 >> 6) * 16384u
                         + sw128((uint32_t)(row & 127) * 128u + (uint32_t)(col8 & 63) * 2u);
            *(uint4*)((char*)g_q + off) = ph.u;
        }
    }
}

// ================================================================================
// Main GEMM via mma.sync fp16 (R11/R13 core — 45us measured) + COALESCED
// EPILOGUE: each warp stages its 32x32 fp32 tile (two 16-row halves) in a
// private smem buffer, then stores full 128B lines via STG.128 (store
// wavefronts per warp-iter: 128 -> 32).
// CTA: 64q x 128k per iter, G=8 k-tiles. A fragments register-resident.
// B double-buffered cp.async. 8 warps, warp tile 32x32, SW128 smem.
// ================================================================================
#define G 8
#define MT3 256
#define SA    0                     // 16 KB A (two 8KB half-slabs)
#define SB    16384                 // 2 x 32 KB B
#define SNSC  81920                 // G x 512 B nscale
#define SST   (SNSC + G * 512)      // 8 x 2304 B per-warp staging
#define STPITCH 144                 // staging row pitch in bytes (16 rows)
#define MAIN_SMEM_BYTES (SST + 8 * 16 * STPITCH)

__device__ __forceinline__ void ldm_x4(uint32_t* r, uint32_t addr) {
    asm volatile("ldmatrix.sync.aligned.m8n8.x4.shared.b16 {%0,%1,%2,%3}, [%4];"
                 : "=r"(r[0]), "=r"(r[1]), "=r"(r[2]), "=r"(r[3])
                 : "r"(addr));
}

__device__ __forceinline__ void mma_fp16(float* d, const uint32_t* a,
                                         uint32_t b0, uint32_t b1) {
    asm volatile(
        "mma.sync.aligned.m16n8k16.row.col.f32.f16.f16.f32 "
        "{%0,%1,%2,%3}, {%4,%5,%6,%7}, {%8,%9}, {%0,%1,%2,%3};"
        : "+f"(d[0]), "+f"(d[1]), "+f"(d[2]), "+f"(d[3])
        : "r"(a[0]), "r"(a[1]), "r"(a[2]), "r"(a[3]), "r"(b0), "r"(b1));
}

__device__ __forceinline__ void cpa16(uint32_t s, const void* g) {
    asm volatile("cp.async.cg.shared.global [%0], [%1], 16;" :: "r"(s), "l"(g));
}
__device__ __forceinline__ void cpa_commit() {
    asm volatile("cp.async.commit_group;");
}

__global__ __launch_bounds__(MT3, 2)
void qjl_mma3_kernel(float* __restrict__ out)
{
    extern __shared__ char smem[];
    uint32_t sb;
    asm("{ .reg .u64 t; cvta.to.shared.u64 t, %1; cvt.u32.u64 %0, t; }"
        : "=r"(sb) : "l"(smem));

    const int tid = threadIdx.x;
    const int warp = tid >> 5, lane = tid & 31;
    const int qtile  = blockIdx.y * 64;
    const int ktile0 = blockIdx.x * (G * 128);

    // ---- group 0: A (16KB = our 64 rows of the 128-row tile, both slabs) ----
    {
        const char* gAbase = (const char*)g_q + (size_t)(qtile >> 7) * 32768
                           + (uint32_t)(qtile & 127) * 128u;
        #pragma unroll
        for (int i = tid; i < 1024; i += MT3) {
            int s = i >> 9, d = (i & 511) * 16;
            cpa16(sb + SA + s * 8192 + d, gAbase + s * 16384 + d);
        }
        cpa_commit();
    }
    // ---- group 1: B0 + all G nscale segments ----
    {
        const char* gB = (const char*)g_signs + (size_t)(ktile0 >> 7) * 32768;
        #pragma unroll
        for (int i = tid; i < 2048; i += MT3)
            cpa16(sb + SB + i * 16, gB + i * 16);
        cpa16(sb + SNSC + tid * 16, (const char*)(g_nscale + ktile0) + tid * 16);
        cpa_commit();
    }

    const int wm = warp >> 2;          // 0..1  (q 32-half)
    const int wn = warp & 3;           // 0..3  (k 32-quarter)
    const int lr = lane & 15;
    const uint32_t lcB = (uint32_t)(lane >> 4) * 16u;

    // ---- wait A, load A fragments ONCE (register-resident across G) ----
    asm volatile("cp.async.wait_group 1;" ::: "memory");
    __syncthreads();

    uint32_t af[8][2][4];
    {
        const uint32_t arow = (uint32_t)(wm * 32 + lr) * 128u + lcB;
        #pragma unroll
        for (int ks = 0; ks < 8; ks++)
            #pragma unroll
            for (int i = 0; i < 2; i++)
                ldm_x4(af[ks][i],
                       sb + SA + (ks >> 2) * 8192
                          + sw128(arow + (uint32_t)i * 2048u + (uint32_t)(ks & 3) * 32u));
    }

    uint32_t brow[2];
    brow[0] = (uint32_t)(wn * 32 + lr) * 128u + lcB;
    brow[1] = brow[0] + 2048u;

    // per-warp staging buffer (generic pointer for C++ accesses)
    char* stg = smem + SST + warp * (16 * STPITCH);

    #pragma unroll 1
    for (int it = 0; it < G; it++) {
        const int kt = ktile0 + it * 128;
        const int buf = it & 1;

        asm volatile("cp.async.wait_group 0;" ::: "memory");
        __syncthreads();   // B[it] visible; all warps done with other buf

        if (it + 1 < G) {  // prefetch B[it+1]
            const int nb = (it + 1) & 1;
            const char* gB = (const char*)g_signs + (size_t)((kt + 128) >> 7) * 32768;
            #pragma unroll
            for (int i = tid; i < 2048; i += MT3)
                cpa16(sb + SB + nb * 32768 + i * 16, gB + i * 16);
            cpa_commit();
        }

        const uint32_t bbase = sb + SB + buf * 32768;
        const float* nscs = (const float*)(smem + SNSC + it * 512);

        float acc[2][4][4];
        #pragma unroll
        for (int i = 0; i < 2; i++)
            #pragma unroll
            for (int j = 0; j < 4; j++)
                #pragma unroll
                for (int t = 0; t < 4; t++) acc[i][j][t] = 0.f;

        #pragma unroll
        for (int ks = 0; ks < 8; ks++) {
            uint32_t bf[2][4];
            #pragma unroll
            for (int jj = 0; jj < 2; jj++)
                ldm_x4(bf[jj], bbase + (ks >> 2) * 16384
                             + sw128(brow[jj] + (uint32_t)(ks & 3) * 32u));
            #pragma unroll
            for (int i = 0; i < 2; i++)
                #pragma unroll
                for (int n8 = 0; n8 < 4; n8++)
                    mma_fp16(acc[i][n8], af[ks][i],
                             bf[n8 >> 1][n8 & 1], bf[n8 >> 1][(n8 & 1) + 2]);
        }

        // ---- coalesced epilogue: stage 16-row half in smem, store 128B lines ----
        const int rr = lane >> 2;                 // 0..7
        const int cbase = 2 * (lane & 3);         // 0,2,4,6
        #pragma unroll
        for (int i = 0; i < 2; i++) {
            // scale + stage (warp-private buffer)
            #pragma unroll
            for (int n8 = 0; n8 < 4; n8++) {
                int cl = wn * 32 + cbase + n8 * 8;       // col in CTA k-tile
                float s0 = nscs[cl], s1 = nscs[cl + 1];
                int scol = cbase + n8 * 8;               // col in warp tile
                *(float2*)(stg + rr * STPITCH + scol * 4) =
                    make_float2(acc[i][n8][0] * s0, acc[i][n8][1] * s1);
                *(float2*)(stg + (rr + 8) * STPITCH + scol * 4) =
                    make_float2(acc[i][n8][2] * s0, acc[i][n8][3] * s1);
            }
            __syncwarp();
            // read back coalesced, store full 128B lines
            const int lrow = lane >> 3;                  // 0..3
            const int lcol = (lane & 7) * 4;             // 0..28
            #pragma unroll
            for (int p = 0; p < 4; p++) {
                int row = lrow + p * 4;                  // 0..15
                float4 v = *(const float4*)(stg + row * STPITCH + lcol * 4);
                int grow = qtile + wm * 32 + i * 16 + row;
                int gcol = kt + wn * 32 + lcol;
                *(float4*)(out + (size_t)grow * NK + gcol) = v;
            }
            __syncwarp();
        }
    }
}

// ================================================================================
extern "C" void kernel_launch(void* const* d_in, const int* in_sizes, int n_in,
                              void* d_out, int out_size)
{
    const float* query    = (const float*)d_in[0];
    const float* residual = (const float*)d_in[1];
    const float* S        = (const float*)d_in[2];
    float* out = (float*)d_out;

    cudaFuncSetAttribute(qjl_prep_kernel,
                         cudaFuncAttributeMaxDynamicSharedMemorySize, PREP_SMEM_BYTES);
    cudaFuncSetAttribute(qjl_mma3_kernel,
                         cudaFuncAttributeMaxDynamicSharedMemorySize, MAIN_SMEM_BYTES);

    // 384 row-blocks x 2 col-halves = 768 blocks, 128 threads, 4 CTAs/SM
    qjl_prep_kernel<<<dim3((NK + NQ) / PREP_ROWS, 2), PREP_THREADS,
                      PREP_SMEM_BYTES>>>(query, residual, S);

    // 8 k-groups x 64 q-tiles = 512 CTAs (2/SM)
    qjl_mma3_kernel<<<dim3(NK / (G * 128), NQ / 64), MT3, MAIN_SMEM_BYTES>>>(out);
}

// round 15
// speedup vs baseline: 1.2281x; 1.2281x over previous
#include <cuda_runtime.h>
#include <cuda_bf16.h>
#include <cuda_fp16.h>
#include <cstdint>

// Problem constants (fixed by the dataset)
#define DHEAD 128
#define MPROJ 128
#define NQ    4096
#define NK    8192
#define SCALE_CONST 0.009791516698f  // sqrt(pi/2)/128

// ---------------- device-global scratch (pre-swizzled SW128 slab layout) -------
// g_q / g_signs: fp16, 128-row tiles of 32KB; two 16KB slabs (64 cols each);
//                slab offset = sw128(row*128 + col*2).
__device__ __half g_signs[NK * MPROJ];
__device__ float  g_nscale[NK];
__device__ __half g_q[NQ * MPROJ];

__device__ __forceinline__ uint32_t sw128(uint32_t x) { return x ^ ((x >> 3) & 0x70); }

// ================================================================================
// Prep (R13 exact — best measured): fp32 GEMM rows @ S^T. Block = 32 rows x
// 64 cols, 128 threads, 2 rows x 8 cols each. fp32 FMA, k ascending (sign
// decisions boundary-sensitive).
//   grid.x [0,256): residual -> signs (fp16 ±1, swizzled) + nscale
//   grid.x [256,384): query  -> q_proj (fp16, swizzled)
//   grid.y: column half
// ================================================================================
#define PREP_ROWS 32
#define PREP_COLS 64
#define PREP_THREADS 128
#define PADP 132
#define PREP_SMEM_BYTES ((PREP_ROWS * PADP + PREP_COLS * PADP) * 4)

__global__ __launch_bounds__(PREP_THREADS)
void qjl_prep_kernel(const float* __restrict__ query,
                     const float* __restrict__ residual,
                     const float* __restrict__ S)
{
    extern __shared__ float smf[];
    float* Ash = smf;                       // [32][132]
    float* Ssh = smf + PREP_ROWS * PADP;    // [64][132]

    const int tid = threadIdx.x;
    const bool is_res = (blockIdx.x < (NK / PREP_ROWS));
    const int rbase = is_res ? blockIdx.x * PREP_ROWS
                             : (blockIdx.x - NK / PREP_ROWS) * PREP_ROWS;
    const int colbase = blockIdx.y * PREP_COLS;
    const float* src = is_res ? residual : query;

    const float4* gA = (const float4*)(src + (size_t)rbase * DHEAD);
    #pragma unroll
    for (int idx = tid; idx < PREP_ROWS * 32; idx += PREP_THREADS) {
        int r = idx >> 5, c4 = idx & 31;
        *(float4*)(Ash + r * PADP + c4 * 4) = gA[idx];
    }
    const float4* gS = (const float4*)(S + (size_t)colbase * DHEAD);
    #pragma unroll
    for (int idx = tid; idx < PREP_COLS * 32; idx += PREP_THREADS) {
        int r = idx >> 5, c4 = idx & 31;
        *(float4*)(Ssh + r * PADP + c4 * 4) = gS[idx];
    }
    __syncthreads();

    if (is_res && blockIdx.y == 0 && tid < PREP_ROWS) {
        float s = 0.f;
        #pragma unroll
        for (int k4 = 0; k4 < 32; k4++) {
            float4 a = *(const float4*)(Ash + tid * PADP + k4 * 4);
            s += a.x * a.x + a.y * a.y + a.z * a.z + a.w * a.w;
        }
        g_nscale[rbase + tid] = sqrtf(s) * SCALE_CONST;
    }

    const int rg = tid & 15;   // 2 rows per thread
    const int cg = tid >> 4;   // 8 cols per thread

    float acc[2][8];
    #pragma unroll
    for (int i = 0; i < 2; i++)
        #pragma unroll
        for (int j = 0; j < 8; j++) acc[i][j] = 0.f;

    const float* arow0 = Ash + (2 * rg) * PADP;
    const float* arow1 = Ash + (2 * rg + 1) * PADP;
    const float* brows = Ssh + (8 * cg) * PADP;

    #pragma unroll 8
    for (int k4 = 0; k4 < 32; k4++) {
        float4 a0 = *(const float4*)(arow0 + k4 * 4);
        float4 a1 = *(const float4*)(arow1 + k4 * 4);
        #pragma unroll
        for (int j = 0; j < 8; j++) {
            float4 b = *(const float4*)(brows + j * PADP + k4 * 4);
            acc[0][j] = fmaf(a0.x, b.x, acc[0][j]);
            acc[0][j] = fmaf(a0.y, b.y, acc[0][j]);
            acc[0][j] = fmaf(a0.z, b.z, acc[0][j]);
            acc[0][j] = fmaf(a0.w, b.w, acc[0][j]);
            acc[1][j] = fmaf(a1.x, b.x, acc[1][j]);
            acc[1][j] = fmaf(a1.y, b.y, acc[1][j]);
            acc[1][j] = fmaf(a1.z, b.z, acc[1][j]);
            acc[1][j] = fmaf(a1.w, b.w, acc[1][j]);
        }
    }

    const int col8 = colbase + 8 * cg;     // global col base (0..120)
    if (is_res) {
        #pragma unroll
        for (int i = 0; i < 2; i++) {
            union { __half h[8]; uint4 u; } pk;
            #pragma unroll
            for (int j = 0; j < 8; j++)
                pk.h[j] = __float2half(acc[i][j] >= 0.f ? 1.f : -1.f);
            int row = rbase + 2 * rg + i;
            uint32_t off = (uint32_t)(row >> 7) * 32768u
                         + (uint32_t)(col8 >> 6) * 16384u
                         + sw128((uint32_t)(row & 127) * 128u + (uint32_t)(col8 & 63) * 2u);
            *(uint4*)((char*)g_signs + off) = pk.u;
        }
    } else {
        #pragma unroll
        for (int i = 0; i < 2; i++) {
            union { __half h[8]; uint4 u; } ph;
            #pragma unroll
            for (int j = 0; j < 8; j++)
                ph.h[j] = __float2half(acc[i][j]);
            int row = rbase + 2 * rg + i;
            uint32_t off = (uint32_t)(row >> 7) * 32768u
                         + (uint32_t)(col8 >> 6) * 16384u
                         + sw128((uint32_t)(row & 127) * 128u + (uint32_t)(col8 & 63) * 2u);
            *(uint4*)((char*)g_q + off) = ph.u;
        }
    }
}

// ================================================================================
// Main GEMM via mma.sync fp16 — BALANCED PERSISTENT PARTITION.
// Grid = 296 CTAs (2/SM x 148). 4096 units (64 q-tiles x 64 k-tiles, q-major)
// split into contiguous ranges (13-14 units/CTA; at most ONE q-boundary per
// range). A fragments register-resident per q (reloaded at most once).
// B + nscale double-buffered cp.async. 8 warps, warp tile 32x32, SW128 smem.
// Coalesced staged epilogue (R14).
// ================================================================================
#define NCTA 296
#define UTOT 4096                   // 64 q x 64 k units
#define MT3 256
#define SA    0                     // 16 KB A (two 8KB half-slabs)
#define SB    16384                 // 2 x 32 KB B
#define SNSC  81920                 // 2 x 512 B nscale
#define SST   (SNSC + 1024)         // 8 x 2304 B per-warp staging
#define STPITCH 144
#define MAIN_SMEM_BYTES (SST + 8 * 16 * STPITCH)

__device__ __forceinline__ void ldm_x4(uint32_t* r, uint32_t addr) {
    asm volatile("ldmatrix.sync.aligned.m8n8.x4.shared.b16 {%0,%1,%2,%3}, [%4];"
                 : "=r"(r[0]), "=r"(r[1]), "=r"(r[2]), "=r"(r[3])
                 : "r"(addr));
}

__device__ __forceinline__ void mma_fp16(float* d, const uint32_t* a,
                                         uint32_t b0, uint32_t b1) {
    asm volatile(
        "mma.sync.aligned.m16n8k16.row.col.f32.f16.f16.f32 "
        "{%0,%1,%2,%3}, {%4,%5,%6,%7}, {%8,%9}, {%0,%1,%2,%3};"
        : "+f"(d[0]), "+f"(d[1]), "+f"(d[2]), "+f"(d[3])
        : "r"(a[0]), "r"(a[1]), "r"(a[2]), "r"(a[3]), "r"(b0), "r"(b1));
}

__device__ __forceinline__ void cpa16(uint32_t s, const void* g) {
    asm volatile("cp.async.cg.shared.global [%0], [%1], 16;" :: "r"(s), "l"(g));
}
__device__ __forceinline__ void cpa_commit() {
    asm volatile("cp.async.commit_group;");
}

__global__ __launch_bounds__(MT3, 2)
void qjl_mma5_kernel(float* __restrict__ out)
{
    extern __shared__ char smem[];
    uint32_t sb;
    asm("{ .reg .u64 t; cvta.to.shared.u64 t, %1; cvt.u32.u64 %0, t; }"
        : "=r"(sb) : "l"(smem));

    const int tid = threadIdx.x;
    const int warp = tid >> 5, lane = tid & 31;
    const int cid = blockIdx.x;
    const int base = (cid * UTOT) / NCTA;
    const int end  = ((cid + 1) * UTOT) / NCTA;

    const int wm = warp >> 2;          // 0..1  (q 32-half)
    const int wn = warp & 3;           // 0..3  (k 32-quarter)
    const int lr = lane & 15;
    const uint32_t lcB = (uint32_t)(lane >> 4) * 16u;

    // ---- prologue: A(q of base) [group], then B(base)+nsc [group] ----
    int qcur = base >> 6;
    {
        const char* gAbase = (const char*)g_q + (size_t)(qcur >> 1) * 32768
                           + (uint32_t)(qcur & 1) * 8192u;
        #pragma unroll
        for (int i = tid; i < 1024; i += MT3) {
            int s = i >> 9, d = (i & 511) * 16;
            cpa16(sb + SA + s * 8192 + d, gAbase + s * 16384 + d);
        }
        cpa_commit();
        const int kt = base & 63;
        const char* gB = (const char*)g_signs + (size_t)kt * 32768;
        #pragma unroll
        for (int i = tid; i < 2048; i += MT3)
            cpa16(sb + SB + i * 16, gB + i * 16);
        if (tid < 32)
            cpa16(sb + SNSC + tid * 16, (const char*)(g_nscale + kt * 128) + tid * 16);
        cpa_commit();
    }

    asm volatile("cp.async.wait_group 1;" ::: "memory");
    __syncthreads();

    // ---- A fragments register-resident ----
    uint32_t af[8][2][4];
    {
        const uint32_t arow = (uint32_t)(wm * 32 + lr) * 128u + lcB;
        #pragma unroll
        for (int ks = 0; ks < 8; ks++)
            #pragma unroll
            for (int i = 0; i < 2; i++)
                ldm_x4(af[ks][i],
                       sb + SA + (ks >> 2) * 8192
                          + sw128(arow + (uint32_t)i * 2048u + (uint32_t)(ks & 3) * 32u));
    }

    uint32_t brow[2];
    brow[0] = (uint32_t)(wn * 32 + lr) * 128u + lcB;
    brow[1] = brow[0] + 2048u;

    char* stg = smem + SST + warp * (16 * STPITCH);
    int qpend = qcur;   // q whose A tile is in smem

    #pragma unroll 1
    for (int i = base; i < end; i++) {
        const int buf = (i - base) & 1;
        const int kt = (i & 63) * 128;

        asm volatile("cp.async.wait_group 0;" ::: "memory");
        __syncthreads();   // B[i] (+A if switched) visible; all warps past buf^1

        if (qpend != qcur) {   // q-boundary: reload A fragments from fresh smem
            qcur = qpend;
            const uint32_t arow = (uint32_t)(wm * 32 + lr) * 128u + lcB;
            #pragma unroll
            for (int ks = 0; ks < 8; ks++)
                #pragma unroll
                for (int ii = 0; ii < 2; ii++)
                    ldm_x4(af[ks][ii],
                           sb + SA + (ks >> 2) * 8192
                              + sw128(arow + (uint32_t)ii * 2048u
                                      + (uint32_t)(ks & 3) * 32u));
        }

        if (i + 1 < end) {   // prefetch unit i+1 (B always; A if q changes)
            const int qn = (i + 1) >> 6;
            if (qn != qpend) {
                qpend = qn;
                const char* gAbase = (const char*)g_q + (size_t)(qn >> 1) * 32768
                                   + (uint32_t)(qn & 1) * 8192u;
                #pragma unroll
                for (int ii = tid; ii < 1024; ii += MT3) {
                    int s = ii >> 9, d = (ii & 511) * 16;
                    cpa16(sb + SA + s * 8192 + d, gAbase + s * 16384 + d);
                }
            }
            const int ktn = (i + 1) & 63;
            const int nb = buf ^ 1;
            const char* gB = (const char*)g_signs + (size_t)ktn * 32768;
            #pragma unroll
            for (int ii = tid; ii < 2048; ii += MT3)
                cpa16(sb + SB + nb * 32768 + ii * 16, gB + ii * 16);
            if (tid < 32)
                cpa16(sb + SNSC + nb * 512 + tid * 16,
                      (const char*)(g_nscale + ktn * 128) + tid * 16);
            cpa_commit();
        }

        const uint32_t bbase = sb + SB + buf * 32768;
        const float* nscs = (const float*)(smem + SNSC + buf * 512);

        float acc[2][4][4];
        #pragma unroll
        for (int ii = 0; ii < 2; ii++)
            #pragma unroll
            for (int j = 0; j < 4; j++)
                #pragma unroll
                for (int t = 0; t < 4; t++) acc[ii][j][t] = 0.f;

        #pragma unroll
        for (int ks = 0; ks < 8; ks++) {
            uint32_t bf[2][4];
            #pragma unroll
            for (int jj = 0; jj < 2; jj++)
                ldm_x4(bf[jj], bbase + (ks >> 2) * 16384
                             + sw128(brow[jj] + (uint32_t)(ks & 3) * 32u));
            #pragma unroll
            for (int ii = 0; ii < 2; ii++)
                #pragma unroll
                for (int n8 = 0; n8 < 4; n8++)
                    mma_fp16(acc[ii][n8], af[ks][ii],
                             bf[n8 >> 1][n8 & 1], bf[n8 >> 1][(n8 & 1) + 2]);
        }

        // ---- coalesced epilogue: stage 16-row halves, store 128B lines ----
        const int qtile = qcur * 64;
        const int rr = lane >> 2;
        const int cbase = 2 * (lane & 3);
        #pragma unroll
        for (int ii = 0; ii < 2; ii++) {
            #pragma unroll
            for (int n8 = 0; n8 < 4; n8++) {
                int cl = wn * 32 + cbase + n8 * 8;
                float s0 = nscs[cl], s1 = nscs[cl + 1];
                int scol = cbase + n8 * 8;
                *(float2*)(stg + rr * STPITCH + scol * 4) =
                    make_float2(acc[ii][n8][0] * s0, acc[ii][n8][1] * s1);
                *(float2*)(stg + (rr + 8) * STPITCH + scol * 4) =
                    make_float2(acc[ii][n8][2] * s0, acc[ii][n8][3] * s1);
            }
            __syncwarp();
            const int lrow = lane >> 3;
            const int lcol = (lane & 7) * 4;
            #pragma unroll
            for (int p = 0; p < 4; p++) {
                int row = lrow + p * 4;
                float4 v = *(const float4*)(stg + row * STPITCH + lcol * 4);
                int grow = qtile + wm * 32 + ii * 16 + row;
                int gcol = kt + wn * 32 + lcol;
                *(float4*)(out + (size_t)grow * NK + gcol) = v;
            }
            __syncwarp();
        }
    }
}

// ================================================================================
extern "C" void kernel_launch(void* const* d_in, const int* in_sizes, int n_in,
                              void* d_out, int out_size)
{
    const float* query    = (const float*)d_in[0];
    const float* residual = (const float*)d_in[1];
    const float* S        = (const float*)d_in[2];
    float* out = (float*)d_out;

    cudaFuncSetAttribute(qjl_prep_kernel,
                         cudaFuncAttributeMaxDynamicSharedMemorySize, PREP_SMEM_BYTES);
    cudaFuncSetAttribute(qjl_mma5_kernel,
                         cudaFuncAttributeMaxDynamicSharedMemorySize, MAIN_SMEM_BYTES);

    // 384 row-blocks x 2 col-halves = 768 blocks, 128 threads, 4 CTAs/SM
    qjl_prep_kernel<<<dim3((NK + NQ) / PREP_ROWS, 2), PREP_THREADS,
                      PREP_SMEM_BYTES>>>(query, residual, S);

    // balanced persistent partition: one clean wave of 296 CTAs
    qjl_mma5_kernel<<<NCTA, MT3, MAIN_SMEM_BYTES>>>(out);
}